// round 9
// baseline (speedup 1.0000x reference)
#include <cuda_runtime.h>
#include <cstdint>

#define TOKENS   16384
#define HIDDEN   4096
#define EXPERTS  64

#define M_TILE   128
#define KC       64
#define NITER    (HIDDEN / KC)     // 64
#define NTHREADS 512

// ---- shared memory layout ----
#define SM_SCALES 64
#define A_TILE_BYTES (M_TILE * 128)     // 16KB: 128 rows x (64B hi | 64B lo) int8
#define B_TILE_BYTES (EXPERTS * 128)    // 8KB: 64 rows x 128B (64B used)
#define SM_A      1024
#define SM_B      (SM_A + 2 * A_TILE_BYTES)    // 33792
#define SM_RED    (SM_B + 2 * B_TILE_BYTES)    // 50176
#define SM_TOTAL  (SM_RED + 32768)             // 82944

// SW128 swizzle (Swizzle<3,4,3>)
#define SW(o) ((o) ^ (((o) >> 3) & 0x70))

// combine coefficients: x ~= q1/16 + q2/(16*254)
#define C_HI  (0.0625f)
#define C_LO  (0.0625f / 254.0f)

// weights repacked to int8 (exact)
__device__ int8_t g_w8[EXPERTS * HIDDEN];

// ---------------- helpers ----------------
__device__ __forceinline__ uint32_t smem_to_u32(const void* p) {
    uint32_t a;
    asm("{ .reg .u64 t; cvta.to.shared.u64 t, %1; cvt.u32.u64 %0, t; }" : "=r"(a) : "l"(p));
    return a;
}
__device__ __forceinline__ void sts32(uint32_t addr, uint32_t a) {
    asm volatile("st.shared.b32 [%0], %1;" :: "r"(addr), "r"(a) : "memory");
}
__device__ __forceinline__ void sts64(uint32_t addr, uint32_t a, uint32_t b) {
    asm volatile("st.shared.v2.b32 [%0], {%1,%2};" :: "r"(addr), "r"(a), "r"(b) : "memory");
}
__device__ __forceinline__ void sts128(uint32_t addr, uint32_t a, uint32_t b,
                                       uint32_t c, uint32_t d) {
    asm volatile("st.shared.v4.b32 [%0], {%1,%2,%3,%4};"
                 :: "r"(addr), "r"(a), "r"(b), "r"(c), "r"(d) : "memory");
}
__device__ __forceinline__ void lds128f(float (&v)[4], uint32_t addr) {
    asm volatile("ld.shared.v4.f32 {%0,%1,%2,%3}, [%4];"
                 : "=f"(v[0]), "=f"(v[1]), "=f"(v[2]), "=f"(v[3]) : "r"(addr));
}
__device__ __forceinline__ void ldsm4(uint32_t (&r)[4], uint32_t addr) {
    asm volatile("ldmatrix.sync.aligned.m8n8.x4.shared.b16 {%0,%1,%2,%3}, [%4];"
                 : "=r"(r[0]), "=r"(r[1]), "=r"(r[2]), "=r"(r[3]) : "r"(addr));
}
__device__ __forceinline__ void imma16832(int (&d)[4], const uint32_t (&a)[4],
                                          uint32_t b0, uint32_t b1) {
    asm volatile("mma.sync.aligned.m16n8k32.row.col.s32.s8.s8.s32 "
                 "{%0,%1,%2,%3}, {%4,%5,%6,%7}, {%8,%9}, {%0,%1,%2,%3};"
                 : "+r"(d[0]), "+r"(d[1]), "+r"(d[2]), "+r"(d[3])
                 : "r"(a[0]), "r"(a[1]), "r"(a[2]), "r"(a[3]), "r"(b0), "r"(b1));
}
__device__ __forceinline__ uint32_t pack4s8(int q0, int q1, int q2, int q3) {
    return (uint32_t)(q0 & 0xFF) | ((uint32_t)(q1 & 0xFF) << 8)
         | ((uint32_t)(q2 & 0xFF) << 16) | ((uint32_t)q3 << 24);
}

// ---------------- kernels ----------------

__global__ void dequant_kernel(const int* __restrict__ w) {
    int t = blockIdx.x * blockDim.x + threadIdx.x;   // 65536 threads, 4 weights each
    int4 v = ((const int4*)w)[t];
    ((uint32_t*)g_w8)[t] = pack4s8(v.x, v.y, v.z, v.w);
}

__global__ void __launch_bounds__(NTHREADS, 1)
gemm_kernel(const float* __restrict__ x,
            const float* __restrict__ scales,
            float* __restrict__ out) {
    extern __shared__ char smem[];
    const uint32_t sbase = smem_to_u32(smem);
    const int tid = threadIdx.x;
    const int wid = tid >> 5;
    const int lid = tid & 31;
    const int m0  = blockIdx.x * M_TILE;

    if (tid < EXPERTS) ((float*)(smem + SM_SCALES))[tid] = scales[tid];
    __syncthreads();

    // ---- producer A (R7 coalescing): warp w stages rows 8w..8w+7.
    //   LDG j covers rows (8w+2j, 8w+2j+1): 4 cache lines per LDG.128.
    const int lsub = lid >> 4;          // 0..1
    const int lcol = lid & 15;          // 0..15 (float4 pieces)
    const float* xA = x + (size_t)(m0 + 8 * wid + lsub) * HIDDEN + lcol * 4;
    uint32_t oAr[4];
#pragma unroll
    for (int j = 0; j < 4; j++)
        oAr[j] = (uint32_t)(8 * wid + 2 * j + lsub) * 128 + lcol * 4;  // int8 hi col

    // ---- producer B: thread -> expert e (0..63), 8-byte octet o
    const int e = tid >> 3;
    const int o = tid & 7;
    const int8_t* wp = g_w8 + (size_t)e * HIDDEN + o * 8;
    const uint32_t oB = (uint32_t)e * 128 + o * 8;

    // ---- consumer: 16 warps = 8 row-groups x 2 k-split groups
    //   warp = 16 rows x 64 experts x 32-wide k-slice (1 IMMA k-step), hi+lo
    const int rg = wid & 7;
    const int kg = wid >> 3;
    const uint32_t aOff = (uint32_t)(16 * rg + (lid & 15)) * 128
                        + (uint32_t)kg * 32 + (uint32_t)(lid >> 4) * 16;
    const uint32_t bOff = (uint32_t)((lid & 7) + ((lid >> 4) << 3)) * 128
                        + (uint32_t)((lid >> 3) & 1) * 16 + (uint32_t)kg * 32;

    int acch[8][4], accl[8][4];
#pragma unroll
    for (int nt = 0; nt < 8; nt++)
#pragma unroll
        for (int j = 0; j < 4; j++) { acch[nt][j] = 0; accl[nt][j] = 0; }

    // 1-deep register prefetch: chunk 0
    float4 an[4]; uint2 bn;
#pragma unroll
    for (int j = 0; j < 4; j++)
        an[j] = *(const float4*)(xA + (size_t)(2 * j) * HIDDEN);
    bn = *(const uint2*)wp;

#pragma unroll 1
    for (int i = 0; i < NITER; i++) {
        const int b = i & 1;
        const uint32_t AB = sbase + SM_A + b * A_TILE_BYTES;
        const uint32_t BB = sbase + SM_B + b * B_TILE_BYTES;

        // ---- stage: quantize each float4 -> 4B hi + 4B lo (int8)
#pragma unroll
        for (int j = 0; j < 4; j++) {
            float4 f = an[j];
            float t0 = f.x * 16.0f, t1 = f.y * 16.0f, t2 = f.z * 16.0f, t3 = f.w * 16.0f;
            int q0 = __float2int_rn(t0), q1 = __float2int_rn(t1);
            int q2 = __float2int_rn(t2), q3 = __float2int_rn(t3);
            int p0 = __float2int_rn((t0 - (float)q0) * 254.0f);
            int p1 = __float2int_rn((t1 - (float)q1) * 254.0f);
            int p2 = __float2int_rn((t2 - (float)q2) * 254.0f);
            int p3 = __float2int_rn((t3 - (float)q3) * 254.0f);
            sts32(AB + SW(oAr[j]),      pack4s8(q0, q1, q2, q3));
            sts32(AB + SW(oAr[j] + 64), pack4s8(p0, p1, p2, p3));
        }
        sts64(BB + SW(oB), bn.x, bn.y);

        // ---- prefetch chunk i+1 (lands during consume)
        if (i + 1 < NITER) {
#pragma unroll
            for (int j = 0; j < 4; j++)
                an[j] = *(const float4*)(xA + (size_t)(2 * j) * HIDDEN + (i + 1) * KC);
            bn = *(const uint2*)(wp + (i + 1) * KC);
        }

        __syncthreads();   // buffer b full; prior consume of b was 2 syncs ago

        // ---- consume: 1 k-step (k32) x 8 expert-tiles, hi+lo
        uint32_t ah[4], al[4];
        ldsm4(ah, AB + SW(aOff));
        ldsm4(al, AB + SW(aOff + 64));
#pragma unroll
        for (int bp = 0; bp < 4; bp++) {
            uint32_t bb[4];
            ldsm4(bb, BB + SW(bOff + (uint32_t)bp * 16 * 128));
            imma16832(acch[2 * bp],     ah, bb[0], bb[1]);
            imma16832(acch[2 * bp + 1], ah, bb[2], bb[3]);
            imma16832(accl[2 * bp],     al, bb[0], bb[1]);
            imma16832(accl[2 * bp + 1], al, bb[2], bb[3]);
        }
    }

    // ---- combine hi/lo into float partials
    float v[8][4];
#pragma unroll
    for (int nt = 0; nt < 8; nt++)
#pragma unroll
        for (int j = 0; j < 4; j++)
            v[nt][j] = (float)acch[nt][j] * C_HI + (float)accl[nt][j] * C_LO;

    // ---- k-split reduction: kg=1 folds into kg=0 via smem
    const uint32_t redW = sbase + SM_RED + (uint32_t)rg * 4096;
    if (kg == 1) {
#pragma unroll
        for (int nt = 0; nt < 8; nt++)
            sts128(redW + (uint32_t)nt * 512 + (uint32_t)lid * 16,
                   __float_as_uint(v[nt][0]), __float_as_uint(v[nt][1]),
                   __float_as_uint(v[nt][2]), __float_as_uint(v[nt][3]));
    }
    __syncthreads();

    // ---- epilogue (kg=0): add partner partials, apply scales, write fp32
    if (kg == 0) {
        const float* sc = (const float*)(smem + SM_SCALES);
        const int rbase = m0 + 16 * rg + (lid >> 2);
        const int cq = 2 * (lid & 3);
#pragma unroll
        for (int nt = 0; nt < 8; nt++) {
            float u[4];
            lds128f(u, redW + (uint32_t)nt * 512 + (uint32_t)lid * 16);
            const int c0 = 8 * nt + cq;
            const float s0 = sc[c0], s1 = sc[c0 + 1];
            float2 v0 = make_float2((v[nt][0] + u[0]) * s0, (v[nt][1] + u[1]) * s1);
            float2 v1 = make_float2((v[nt][2] + u[2]) * s0, (v[nt][3] + u[3]) * s1);
            *(float2*)(out + (size_t)rbase * EXPERTS + c0)       = v0;
            *(float2*)(out + (size_t)(rbase + 8) * EXPERTS + c0) = v1;
        }
    }
}

extern "C" void kernel_launch(void* const* d_in, const int* in_sizes, int n_in,
                              void* d_out, int out_size) {
    const float* x      = (const float*)d_in[0];
    const int*   w      = (const int*)d_in[1];
    const float* scales = (const float*)d_in[2];
    float* out = (float*)d_out;

    cudaFuncSetAttribute(gemm_kernel, cudaFuncAttributeMaxDynamicSharedMemorySize, SM_TOTAL);

    dequant_kernel<<<256, 256>>>(w);                 // int32 weights -> int8 (exact)
    gemm_kernel<<<TOKENS / M_TILE, NTHREADS, SM_TOTAL>>>(x, scales, out);
}

// round 10
// speedup vs baseline: 2.7050x; 2.7050x over previous
#include <cuda_runtime.h>
#include <cuda_bf16.h>
#include <cstdint>

#define TOKENS   16384
#define HIDDEN   4096
#define EXPERTS  64

#define M_TILE   128
#define KC       64
#define NITER    (HIDDEN / KC)     // 64
#define NTHREADS 512
#define NSTAGE   3

// ---- shared memory layout ----
// per stage: A_hi 16KB | A_lo 16KB | B 8KB
#define STG_BYTES 40960
#define A_LO_OFF  16384
#define B_OFF     32768
#define SM_MBAR   8                       // 6 mbarriers (full/empty x 3), 16B/stage
#define SM_SCALES 256
#define SM_STG    1024
#define SM_RED    (SM_STG + NSTAGE * STG_BYTES)   // 123904
#define SM_TOTAL  (SM_RED + 32768)                // 156672

// SW128 swizzle (Swizzle<3,4,3>)
#define SW(o) ((o) ^ (((o) >> 3) & 0x70))

// dequantized weights (int8 exact in bf16; scale folded into epilogue)
__device__ __nv_bfloat16 g_wb[EXPERTS * HIDDEN];

// ---------------- helpers ----------------
__device__ __forceinline__ uint32_t smem_to_u32(const void* p) {
    uint32_t a;
    asm("{ .reg .u64 t; cvta.to.shared.u64 t, %1; cvt.u32.u64 %0, t; }" : "=r"(a) : "l"(p));
    return a;
}
__device__ __forceinline__ void sts64(uint32_t addr, uint32_t a, uint32_t b) {
    asm volatile("st.shared.v2.b32 [%0], {%1,%2};" :: "r"(addr), "r"(a), "r"(b) : "memory");
}
__device__ __forceinline__ void sts128(uint32_t addr, uint32_t a, uint32_t b,
                                       uint32_t c, uint32_t d) {
    asm volatile("st.shared.v4.b32 [%0], {%1,%2,%3,%4};"
                 :: "r"(addr), "r"(a), "r"(b), "r"(c), "r"(d) : "memory");
}
__device__ __forceinline__ void lds128f(float (&v)[4], uint32_t addr) {
    asm volatile("ld.shared.v4.f32 {%0,%1,%2,%3}, [%4];"
                 : "=f"(v[0]), "=f"(v[1]), "=f"(v[2]), "=f"(v[3]) : "r"(addr));
}
__device__ __forceinline__ uint32_t pack_bf16(float lo, float hi) {
    uint32_t r;
    asm("cvt.rn.bf16x2.f32 %0, %1, %2;" : "=r"(r) : "f"(hi), "f"(lo));
    return r;
}
__device__ __forceinline__ float bf_lo(uint32_t p) { return __uint_as_float(p << 16); }
__device__ __forceinline__ float bf_hi(uint32_t p) { return __uint_as_float(p & 0xffff0000u); }

__device__ __forceinline__ void ldsm4(uint32_t (&r)[4], uint32_t addr) {
    asm volatile("ldmatrix.sync.aligned.m8n8.x4.shared.b16 {%0,%1,%2,%3}, [%4];"
                 : "=r"(r[0]), "=r"(r[1]), "=r"(r[2]), "=r"(r[3]) : "r"(addr));
}
__device__ __forceinline__ void mma16816(float (&d)[4], const uint32_t (&a)[4],
                                         uint32_t b0, uint32_t b1) {
    asm volatile("mma.sync.aligned.m16n8k16.row.col.f32.bf16.bf16.f32 "
                 "{%0,%1,%2,%3}, {%4,%5,%6,%7}, {%8,%9}, {%0,%1,%2,%3};"
                 : "+f"(d[0]), "+f"(d[1]), "+f"(d[2]), "+f"(d[3])
                 : "r"(a[0]), "r"(a[1]), "r"(a[2]), "r"(a[3]), "r"(b0), "r"(b1));
}

#define MBARRIER_INIT(mbar, count) \
    asm volatile("mbarrier.init.shared.b64 [%0], %1;" \
                 :: "r"((uint32_t)(mbar)), "r"((uint32_t)(count)) : "memory")
#define MBARRIER_ARRIVE(mbar) \
    asm volatile("mbarrier.arrive.shared.b64 _, [%0];" :: "r"((uint32_t)(mbar)) : "memory")
#define MBARRIER_WAIT_PARITY(mbar_smem_addr, phase_parity) do { \
    uint32_t _mbar = (uint32_t)(mbar_smem_addr); \
    uint32_t _parity = (uint32_t)(phase_parity); \
    uint32_t _done; \
    asm volatile("{\n\t.reg .pred p;\n\t" \
        "mbarrier.try_wait.parity.shared.b64 p, [%1], %2;\n\t" \
        "selp.b32 %0, 1, 0, p;\n\t}" \
        : "=r"(_done) : "r"(_mbar), "r"(_parity) : "memory"); \
    if (!_done) { \
        asm volatile("{\n\t.reg .pred P1;\n\t" \
            "WAIT_LOOP_%=:\n\t" \
            "mbarrier.try_wait.parity.shared.b64 P1, [%0], %1, 0x989680;\n\t" \
            "@P1 bra.uni WAIT_DONE_%=;\n\t" \
            "bra.uni WAIT_LOOP_%=;\n\t" \
            "WAIT_DONE_%=:\n\t}" \
            :: "r"(_mbar), "r"(_parity) : "memory"); \
    } \
} while (0)

// ---------------- kernels ----------------

__global__ void dequant_kernel(const int* __restrict__ w) {
    int t = blockIdx.x * blockDim.x + threadIdx.x;        // 0..65535
    int4 v = ((const int4*)w)[t];
    __nv_bfloat162 p0 = __floats2bfloat162_rn((float)v.x, (float)v.y);
    __nv_bfloat162 p1 = __floats2bfloat162_rn((float)v.z, (float)v.w);
    ((__nv_bfloat162*)g_wb)[2 * t]     = p0;
    ((__nv_bfloat162*)g_wb)[2 * t + 1] = p1;
}

struct ProdCtx {
    const float* xA;                 // base for A loads (row pair stride 2*HIDDEN)
    const __nv_bfloat16* wpB;        // base for B loads
    uint32_t oAr0;                   // STS offset for j=0 (stride 2*128 per j)
    uint32_t oB;
};

__device__ __forceinline__ void prod_prefetch(const ProdCtx& c, int chunk,
                                              float4 (&a)[8], uint4 (&b)[2]) {
#pragma unroll
    for (int j = 0; j < 8; j++)
        a[j] = *(const float4*)(c.xA + (size_t)(2 * j) * HIDDEN + chunk * KC);
    const uint4* pb = (const uint4*)(c.wpB + chunk * KC);
    b[0] = pb[0]; b[1] = pb[1];
}

__device__ __forceinline__ void prod_stage(const ProdCtx& c, const float4 (&a)[8],
                                           const uint4 (&b)[2], uint32_t stg) {
    const uint32_t AH = stg, AL = stg + A_LO_OFF, BB = stg + B_OFF;
#pragma unroll
    for (int j = 0; j < 8; j++) {
        float4 f = a[j];
        uint32_t h0 = pack_bf16(f.x, f.y);
        uint32_t h1 = pack_bf16(f.z, f.w);
        float lx = f.x - bf_lo(h0);
        float ly = f.y - bf_hi(h0);
        float lz = f.z - bf_lo(h1);
        float lw = f.w - bf_hi(h1);
        uint32_t l0 = pack_bf16(lx, ly);
        uint32_t l1 = pack_bf16(lz, lw);
        uint32_t o = c.oAr0 + (uint32_t)j * 256;
        sts64(AH + SW(o), h0, h1);
        sts64(AL + SW(o), l0, l1);
    }
    sts128(BB + SW(c.oB),      b[0].x, b[0].y, b[0].z, b[0].w);
    sts128(BB + SW(c.oB + 16), b[1].x, b[1].y, b[1].z, b[1].w);
}

__global__ void __launch_bounds__(NTHREADS, 1)
gemm_kernel(const float* __restrict__ x,
            const float* __restrict__ scales,
            float* __restrict__ out) {
    extern __shared__ char smem[];
    const uint32_t sbase = smem_to_u32(smem);
    const int tid = threadIdx.x;
    const int wid = tid >> 5;
    const int lid = tid & 31;
    const int m0  = blockIdx.x * M_TILE;

    if (tid == 0) {
#pragma unroll
        for (int s = 0; s < NSTAGE; s++) {
            MBARRIER_INIT(sbase + SM_MBAR + s * 16,     8);   // full[s]: 8 producer warps
            MBARRIER_INIT(sbase + SM_MBAR + s * 16 + 8, 8);   // empty[s]: 8 consumer warps
        }
    }
    if (tid < EXPERTS) ((float*)(smem + SM_SCALES))[tid] = scales[tid];
    __syncthreads();

    if (wid < 8) {
        // ================= PRODUCER (warps 0-7) =================
        // A: warp w stages rows 16w..16w+15; LDG j covers rows (16w+2j, 16w+2j+1):
        //    thread -> row +lsub, 16B piece lcol => 4 cache lines per LDG.128.
        const int lsub = lid >> 4, lcol = lid & 15;
        ProdCtx c;
        c.xA   = x + (size_t)(m0 + 16 * wid + lsub) * HIDDEN + lcol * 4;
        c.oAr0 = (uint32_t)(16 * wid + lsub) * 128 + lcol * 8;
        // B: thread t (0..255) -> expert e=t>>2, 32B piece p=t&3
        const int e = tid >> 2, p = tid & 3;
        c.wpB = g_wb + (size_t)e * HIDDEN + p * 16;
        c.oB  = (uint32_t)e * 128 + p * 32;

        float4 a0[8], a1[8]; uint4 b0[2], b1[2];
        prod_prefetch(c, 0, a0, b0);
        prod_prefetch(c, 1, a1, b1);

        int ps = 0, pph = 1;   // producer phase starts at 1: first empty-wait passes
#pragma unroll 1
        for (int i = 0; i < NITER; i += 2) {
            MBARRIER_WAIT_PARITY(sbase + SM_MBAR + ps * 16 + 8, pph);
            prod_stage(c, a0, b0, sbase + SM_STG + ps * STG_BYTES);
            __syncwarp();
            if (lid == 0) MBARRIER_ARRIVE(sbase + SM_MBAR + ps * 16);
            if (++ps == NSTAGE) { ps = 0; pph ^= 1; }
            if (i + 2 < NITER) prod_prefetch(c, i + 2, a0, b0);

            MBARRIER_WAIT_PARITY(sbase + SM_MBAR + ps * 16 + 8, pph);
            prod_stage(c, a1, b1, sbase + SM_STG + ps * STG_BYTES);
            __syncwarp();
            if (lid == 0) MBARRIER_ARRIVE(sbase + SM_MBAR + ps * 16);
            if (++ps == NSTAGE) { ps = 0; pph ^= 1; }
            if (i + 3 < NITER) prod_prefetch(c, i + 3, a1, b1);
        }
        __syncthreads();  // join tail
        __syncthreads();
    } else {
        // ================= CONSUMER (warps 8-15) =================
        // 8 warps = 4 row-groups x 2 k-split; warp = 32 rows x 64 experts x 32k
        const int cw = wid - 8;
        const int rg = cw & 3;
        const int kg = cw >> 2;

        uint32_t aRel[2][2], bRel[4][2];
#pragma unroll
        for (int mt = 0; mt < 2; mt++)
#pragma unroll
            for (int ks = 0; ks < 2; ks++)
                aRel[mt][ks] = (uint32_t)(32 * rg + 16 * mt + (lid & 15)) * 128
                             + (uint32_t)kg * 64 + (uint32_t)ks * 32
                             + (uint32_t)(lid >> 4) * 16;
#pragma unroll
        for (int nt = 0; nt < 4; nt++)
#pragma unroll
            for (int ks = 0; ks < 2; ks++)
                bRel[nt][ks] = (uint32_t)(16 * nt + (lid & 7) + ((lid >> 4) << 3)) * 128
                             + (uint32_t)kg * 64 + (uint32_t)ks * 32
                             + (uint32_t)((lid >> 3) & 1) * 16;

        float acc[2][8][4];
#pragma unroll
        for (int mt = 0; mt < 2; mt++)
#pragma unroll
            for (int nt = 0; nt < 8; nt++)
#pragma unroll
                for (int j = 0; j < 4; j++) acc[mt][nt][j] = 0.0f;

        int cs = 0, cph = 0;
#pragma unroll 1
        for (int i = 0; i < NITER; i++) {
            MBARRIER_WAIT_PARITY(sbase + SM_MBAR + cs * 16, cph);
            const uint32_t stg = sbase + SM_STG + cs * STG_BYTES;
            const uint32_t AH = stg, AL = stg + A_LO_OFF, BB = stg + B_OFF;
#pragma unroll
            for (int ks = 0; ks < 2; ks++) {
                uint32_t ah[2][4], al[2][4];
                ldsm4(ah[0], AH + SW(aRel[0][ks]));
                ldsm4(ah[1], AH + SW(aRel[1][ks]));
                ldsm4(al[0], AL + SW(aRel[0][ks]));
                ldsm4(al[1], AL + SW(aRel[1][ks]));
#pragma unroll
                for (int nt = 0; nt < 4; nt++) {
                    uint32_t bb[4];
                    ldsm4(bb, BB + SW(bRel[nt][ks]));
#pragma unroll
                    for (int mt = 0; mt < 2; mt++) {
                        mma16816(acc[mt][2 * nt],     ah[mt], bb[0], bb[1]);
                        mma16816(acc[mt][2 * nt + 1], ah[mt], bb[2], bb[3]);
                        mma16816(acc[mt][2 * nt],     al[mt], bb[0], bb[1]);
                        mma16816(acc[mt][2 * nt + 1], al[mt], bb[2], bb[3]);
                    }
                }
            }
            __syncwarp();
            if (lid == 0) MBARRIER_ARRIVE(sbase + SM_MBAR + cs * 16 + 8);
            if (++cs == NSTAGE) { cs = 0; cph ^= 1; }
        }

        // ---- k-split fold: kg=1 dumps, kg=0 adds + writes
        const uint32_t redW = sbase + SM_RED + (uint32_t)rg * 8192;
        if (kg == 1) {
#pragma unroll
            for (int mt = 0; mt < 2; mt++)
#pragma unroll
                for (int nt = 0; nt < 8; nt++)
                    sts128(redW + (uint32_t)(mt * 8 + nt) * 512 + (uint32_t)lid * 16,
                           __float_as_uint(acc[mt][nt][0]), __float_as_uint(acc[mt][nt][1]),
                           __float_as_uint(acc[mt][nt][2]), __float_as_uint(acc[mt][nt][3]));
        }
        __syncthreads();
        if (kg == 0) {
            const float* sc = (const float*)(smem + SM_SCALES);
            const int cq = 2 * (lid & 3);
#pragma unroll
            for (int mt = 0; mt < 2; mt++) {
                const int rbase = m0 + 32 * rg + 16 * mt + (lid >> 2);
#pragma unroll
                for (int nt = 0; nt < 8; nt++) {
                    float u[4];
                    lds128f(u, redW + (uint32_t)(mt * 8 + nt) * 512 + (uint32_t)lid * 16);
                    const int c0 = 8 * nt + cq;
                    const float s0 = sc[c0], s1 = sc[c0 + 1];
                    float2 v0 = make_float2((acc[mt][nt][0] + u[0]) * s0,
                                            (acc[mt][nt][1] + u[1]) * s1);
                    float2 v1 = make_float2((acc[mt][nt][2] + u[2]) * s0,
                                            (acc[mt][nt][3] + u[3]) * s1);
                    *(float2*)(out + (size_t)rbase * EXPERTS + c0)       = v0;
                    *(float2*)(out + (size_t)(rbase + 8) * EXPERTS + c0) = v1;
                }
            }
        }
        __syncthreads();
    }
}

extern "C" void kernel_launch(void* const* d_in, const int* in_sizes, int n_in,
                              void* d_out, int out_size) {
    const float* x      = (const float*)d_in[0];
    const int*   w      = (const int*)d_in[1];
    const float* scales = (const float*)d_in[2];
    float* out = (float*)d_out;

    cudaFuncSetAttribute(gemm_kernel, cudaFuncAttributeMaxDynamicSharedMemorySize, SM_TOTAL);

    dequant_kernel<<<256, 256>>>(w);                 // int32 weights -> bf16 (exact)
    gemm_kernel<<<TOKENS / M_TILE, NTHREADS, SM_TOTAL>>>(x, scales, out);
}

// round 11
// speedup vs baseline: 2.8980x; 1.0713x over previous
#include <cuda_runtime.h>
#include <cuda_fp16.h>
#include <cstdint>

#define TOKENS   16384
#define HIDDEN   4096
#define EXPERTS  64

#define M_TILE   128
#define KC       64
#define NITER    (HIDDEN / KC)     // 64
#define NTHREADS 512
#define NSTAGE   4

// ---- shared memory layout ----
// per stage: A 16KB | B 8KB   (fp16)
#define STG_BYTES 24576
#define B_OFF     16384
#define SM_MBAR   8                       // full/empty pairs, 16B per stage
#define SM_SCALES 256
#define SM_STG    1024
#define SM_RED    (SM_STG + NSTAGE * STG_BYTES)   // 99328
#define SM_TOTAL  (SM_RED + 32768)                // 132096

// SW128 swizzle (Swizzle<3,4,3>)
#define SW(o) ((o) ^ (((o) >> 3) & 0x70))

// weights as fp16 (int8 values exact in fp16; scale folded into epilogue)
__device__ __half g_wh[EXPERTS * HIDDEN];

// ---------------- helpers ----------------
__device__ __forceinline__ uint32_t smem_to_u32(const void* p) {
    uint32_t a;
    asm("{ .reg .u64 t; cvta.to.shared.u64 t, %1; cvt.u32.u64 %0, t; }" : "=r"(a) : "l"(p));
    return a;
}
__device__ __forceinline__ void sts64(uint32_t addr, uint32_t a, uint32_t b) {
    asm volatile("st.shared.v2.b32 [%0], {%1,%2};" :: "r"(addr), "r"(a), "r"(b) : "memory");
}
__device__ __forceinline__ void sts128(uint32_t addr, uint32_t a, uint32_t b,
                                       uint32_t c, uint32_t d) {
    asm volatile("st.shared.v4.b32 [%0], {%1,%2,%3,%4};"
                 :: "r"(addr), "r"(a), "r"(b), "r"(c), "r"(d) : "memory");
}
__device__ __forceinline__ void lds128f(float (&v)[4], uint32_t addr) {
    asm volatile("ld.shared.v4.f32 {%0,%1,%2,%3}, [%4];"
                 : "=f"(v[0]), "=f"(v[1]), "=f"(v[2]), "=f"(v[3]) : "r"(addr));
}
// pack_f16(lo, hi): low half-word = f16(lo), high = f16(hi)
__device__ __forceinline__ uint32_t pack_f16(float lo, float hi) {
    uint32_t r;
    asm("cvt.rn.f16x2.f32 %0, %1, %2;" : "=r"(r) : "f"(hi), "f"(lo));
    return r;
}
__device__ __forceinline__ void ldsm4(uint32_t (&r)[4], uint32_t addr) {
    asm volatile("ldmatrix.sync.aligned.m8n8.x4.shared.b16 {%0,%1,%2,%3}, [%4];"
                 : "=r"(r[0]), "=r"(r[1]), "=r"(r[2]), "=r"(r[3]) : "r"(addr));
}
__device__ __forceinline__ void mma16816(float (&d)[4], const uint32_t (&a)[4],
                                         uint32_t b0, uint32_t b1) {
    asm volatile("mma.sync.aligned.m16n8k16.row.col.f32.f16.f16.f32 "
                 "{%0,%1,%2,%3}, {%4,%5,%6,%7}, {%8,%9}, {%0,%1,%2,%3};"
                 : "+f"(d[0]), "+f"(d[1]), "+f"(d[2]), "+f"(d[3])
                 : "r"(a[0]), "r"(a[1]), "r"(a[2]), "r"(a[3]), "r"(b0), "r"(b1));
}

#define MBARRIER_INIT(mbar, count) \
    asm volatile("mbarrier.init.shared.b64 [%0], %1;" \
                 :: "r"((uint32_t)(mbar)), "r"((uint32_t)(count)) : "memory")
#define MBARRIER_ARRIVE(mbar) \
    asm volatile("mbarrier.arrive.shared.b64 _, [%0];" :: "r"((uint32_t)(mbar)) : "memory")
#define MBARRIER_WAIT_PARITY(mbar_smem_addr, phase_parity) do { \
    uint32_t _mbar = (uint32_t)(mbar_smem_addr); \
    uint32_t _parity = (uint32_t)(phase_parity); \
    uint32_t _done; \
    asm volatile("{\n\t.reg .pred p;\n\t" \
        "mbarrier.try_wait.parity.shared.b64 p, [%1], %2;\n\t" \
        "selp.b32 %0, 1, 0, p;\n\t}" \
        : "=r"(_done) : "r"(_mbar), "r"(_parity) : "memory"); \
    if (!_done) { \
        asm volatile("{\n\t.reg .pred P1;\n\t" \
            "WAIT_LOOP_%=:\n\t" \
            "mbarrier.try_wait.parity.shared.b64 P1, [%0], %1, 0x989680;\n\t" \
            "@P1 bra.uni WAIT_DONE_%=;\n\t" \
            "bra.uni WAIT_LOOP_%=;\n\t" \
            "WAIT_DONE_%=:\n\t}" \
            :: "r"(_mbar), "r"(_parity) : "memory"); \
    } \
} while (0)

// ---------------- kernels ----------------

__global__ void dequant_kernel(const int* __restrict__ w) {
    int t = blockIdx.x * blockDim.x + threadIdx.x;        // 0..65535, 4 weights each
    int4 v = ((const int4*)w)[t];
    uint2 p;
    p.x = pack_f16((float)v.x, (float)v.y);
    p.y = pack_f16((float)v.z, (float)v.w);
    ((uint2*)g_wh)[t] = p;
}

struct ProdCtx {
    const float* xA;                 // base for A loads (row-pair stride 2*HIDDEN)
    const __half* wpB;               // base for B loads
    uint32_t oAr0;                   // STS offset for j=0 (stride 256B per j)
    uint32_t oB;
};

__device__ __forceinline__ void prod_prefetch(const ProdCtx& c, int chunk,
                                              float4 (&a)[8], uint4 (&b)[2]) {
#pragma unroll
    for (int j = 0; j < 8; j++)
        a[j] = *(const float4*)(c.xA + (size_t)(2 * j) * HIDDEN + chunk * KC);
    const uint4* pb = (const uint4*)(c.wpB + chunk * KC);
    b[0] = pb[0]; b[1] = pb[1];
}

__device__ __forceinline__ void prod_stage(const ProdCtx& c, const float4 (&a)[8],
                                           const uint4 (&b)[2], uint32_t stg) {
    const uint32_t AH = stg, BB = stg + B_OFF;
#pragma unroll
    for (int j = 0; j < 8; j++) {
        float4 f = a[j];
        uint32_t h0 = pack_f16(f.x, f.y);
        uint32_t h1 = pack_f16(f.z, f.w);
        sts64(AH + SW(c.oAr0 + (uint32_t)j * 256), h0, h1);
    }
    sts128(BB + SW(c.oB),      b[0].x, b[0].y, b[0].z, b[0].w);
    sts128(BB + SW(c.oB + 16), b[1].x, b[1].y, b[1].z, b[1].w);
}

__global__ void __launch_bounds__(NTHREADS, 1)
gemm_kernel(const float* __restrict__ x,
            const float* __restrict__ scales,
            float* __restrict__ out) {
    extern __shared__ char smem[];
    const uint32_t sbase = smem_to_u32(smem);
    const int tid = threadIdx.x;
    const int wid = tid >> 5;
    const int lid = tid & 31;
    const int m0  = blockIdx.x * M_TILE;

    if (tid == 0) {
#pragma unroll
        for (int s = 0; s < NSTAGE; s++) {
            MBARRIER_INIT(sbase + SM_MBAR + s * 16,     8);   // full[s]: 8 producer warps
            MBARRIER_INIT(sbase + SM_MBAR + s * 16 + 8, 8);   // empty[s]: 8 consumer warps
        }
    }
    if (tid < EXPERTS) ((float*)(smem + SM_SCALES))[tid] = scales[tid];
    __syncthreads();

    if (wid < 8) {
        // ================= PRODUCER (warps 0-7) =================
        // A: warp w stages rows 16w..16w+15; LDG j covers rows (16w+2j, 16w+2j+1):
        //    thread -> row +lsub, 16B piece lcol => 4 cache lines per LDG.128.
        const int lsub = lid >> 4, lcol = lid & 15;
        ProdCtx c;
        c.xA   = x + (size_t)(m0 + 16 * wid + lsub) * HIDDEN + lcol * 4;
        c.oAr0 = (uint32_t)(16 * wid + lsub) * 128 + lcol * 8;
        // B: thread t (0..255) -> expert e=t>>2, 32B piece p=t&3
        const int e = tid >> 2, p = tid & 3;
        c.wpB = g_wh + (size_t)e * HIDDEN + p * 16;
        c.oB  = (uint32_t)e * 128 + p * 32;

        float4 a0[8], a1[8]; uint4 b0[2], b1[2];
        prod_prefetch(c, 0, a0, b0);
        prod_prefetch(c, 1, a1, b1);

        int ps = 0, pph = 1;   // producer phase starts at 1: first empty-wait passes
#pragma unroll 1
        for (int i = 0; i < NITER; i += 2) {
            MBARRIER_WAIT_PARITY(sbase + SM_MBAR + ps * 16 + 8, pph);
            prod_stage(c, a0, b0, sbase + SM_STG + ps * STG_BYTES);
            __syncwarp();
            if (lid == 0) MBARRIER_ARRIVE(sbase + SM_MBAR + ps * 16);
            if (++ps == NSTAGE) { ps = 0; pph ^= 1; }
            if (i + 2 < NITER) prod_prefetch(c, i + 2, a0, b0);

            MBARRIER_WAIT_PARITY(sbase + SM_MBAR + ps * 16 + 8, pph);
            prod_stage(c, a1, b1, sbase + SM_STG + ps * STG_BYTES);
            __syncwarp();
            if (lid == 0) MBARRIER_ARRIVE(sbase + SM_MBAR + ps * 16);
            if (++ps == NSTAGE) { ps = 0; pph ^= 1; }
            if (i + 3 < NITER) prod_prefetch(c, i + 3, a1, b1);
        }
        __syncthreads();  // join tail
        __syncthreads();
    } else {
        // ================= CONSUMER (warps 8-15) =================
        // 8 warps = 4 row-groups x 2 k-split; warp = 32 rows x 64 experts x 32k
        const int cw = wid - 8;
        const int rg = cw & 3;
        const int kg = cw >> 2;

        uint32_t aRel[2][2], bRel[4][2];
#pragma unroll
        for (int mt = 0; mt < 2; mt++)
#pragma unroll
            for (int ks = 0; ks < 2; ks++)
                aRel[mt][ks] = (uint32_t)(32 * rg + 16 * mt + (lid & 15)) * 128
                             + (uint32_t)kg * 64 + (uint32_t)ks * 32
                             + (uint32_t)(lid >> 4) * 16;
#pragma unroll
        for (int nt = 0; nt < 4; nt++)
#pragma unroll
            for (int ks = 0; ks < 2; ks++)
                bRel[nt][ks] = (uint32_t)(16 * nt + (lid & 7) + ((lid >> 4) << 3)) * 128
                             + (uint32_t)kg * 64 + (uint32_t)ks * 32
                             + (uint32_t)((lid >> 3) & 1) * 16;

        float acc[2][8][4];
#pragma unroll
        for (int mt = 0; mt < 2; mt++)
#pragma unroll
            for (int nt = 0; nt < 8; nt++)
#pragma unroll
                for (int j = 0; j < 4; j++) acc[mt][nt][j] = 0.0f;

        int cs = 0, cph = 0;
#pragma unroll 1
        for (int i = 0; i < NITER; i++) {
            MBARRIER_WAIT_PARITY(sbase + SM_MBAR + cs * 16, cph);
            const uint32_t stg = sbase + SM_STG + cs * STG_BYTES;
            const uint32_t AH = stg, BB = stg + B_OFF;
#pragma unroll
            for (int ks = 0; ks < 2; ks++) {
                uint32_t ah[2][4];
                ldsm4(ah[0], AH + SW(aRel[0][ks]));
                ldsm4(ah[1], AH + SW(aRel[1][ks]));
#pragma unroll
                for (int nt = 0; nt < 4; nt++) {
                    uint32_t bb[4];
                    ldsm4(bb, BB + SW(bRel[nt][ks]));
#pragma unroll
                    for (int mt = 0; mt < 2; mt++) {
                        mma16816(acc[mt][2 * nt],     ah[mt], bb[0], bb[1]);
                        mma16816(acc[mt][2 * nt + 1], ah[mt], bb[2], bb[3]);
                    }
                }
            }
            __syncwarp();
            if (lid == 0) MBARRIER_ARRIVE(sbase + SM_MBAR + cs * 16 + 8);
            if (++cs == NSTAGE) { cs = 0; cph ^= 1; }
        }

        // ---- k-split fold: kg=1 dumps, kg=0 adds + writes
        const uint32_t redW = sbase + SM_RED + (uint32_t)rg * 8192;
        if (kg == 1) {
#pragma unroll
            for (int mt = 0; mt < 2; mt++)
#pragma unroll
                for (int nt = 0; nt < 8; nt++)
                    sts128(redW + (uint32_t)(mt * 8 + nt) * 512 + (uint32_t)lid * 16,
                           __float_as_uint(acc[mt][nt][0]), __float_as_uint(acc[mt][nt][1]),
                           __float_as_uint(acc[mt][nt][2]), __float_as_uint(acc[mt][nt][3]));
        }
        __syncthreads();
        if (kg == 0) {
            const float* sc = (const float*)(smem + SM_SCALES);
            const int cq = 2 * (lid & 3);
#pragma unroll
            for (int mt = 0; mt < 2; mt++) {
                const int rbase = m0 + 32 * rg + 16 * mt + (lid >> 2);
#pragma unroll
                for (int nt = 0; nt < 8; nt++) {
                    float u[4];
                    lds128f(u, redW + (uint32_t)(mt * 8 + nt) * 512 + (uint32_t)lid * 16);
                    const int c0 = 8 * nt + cq;
                    const float s0 = sc[c0], s1 = sc[c0 + 1];
                    float2 v0 = make_float2((acc[mt][nt][0] + u[0]) * s0,
                                            (acc[mt][nt][1] + u[1]) * s1);
                    float2 v1 = make_float2((acc[mt][nt][2] + u[2]) * s0,
                                            (acc[mt][nt][3] + u[3]) * s1);
                    *(float2*)(out + (size_t)rbase * EXPERTS + c0)       = v0;
                    *(float2*)(out + (size_t)(rbase + 8) * EXPERTS + c0) = v1;
                }
            }
        }
        __syncthreads();
    }
}

extern "C" void kernel_launch(void* const* d_in, const int* in_sizes, int n_in,
                              void* d_out, int out_size) {
    const float* x      = (const float*)d_in[0];
    const int*   w      = (const int*)d_in[1];
    const float* scales = (const float*)d_in[2];
    float* out = (float*)d_out;

    cudaFuncSetAttribute(gemm_kernel, cudaFuncAttributeMaxDynamicSharedMemorySize, SM_TOTAL);

    dequant_kernel<<<256, 256>>>(w);                 // int32 weights -> fp16 (exact)
    gemm_kernel<<<TOKENS / M_TILE, NTHREADS, SM_TOTAL>>>(x, scales, out);
}